// round 1
// baseline (speedup 1.0000x reference)
#include <cuda_runtime.h>
#include <math.h>

#define B_  2
#define S_  2048
#define D_  2048
#define H_  16
#define HD_ 128

// ---------------- scratch (static device globals; no runtime allocation) ----
__device__ float g_q[B_*S_*D_];      // [B,S,H,HD] post-projection / post-RoPE
__device__ float g_k[B_*S_*HD_];     // [B,S,HD]
__device__ float g_v[B_*S_*HD_];     // [B,S,HD]
__device__ float g_attn[B_*S_*D_];   // attention output in [B,S,H*HD] layout

// ---------------------------------------------------------------------------
// SGEMM: C[m][n] = sum_k A[m][k] * Bm[n][k]   (both operands K-major)
// 128x128 block tile, BK=16, 256 threads, 8x8 per-thread micro-tile.
// M,N,K must be multiples of 128/128/16 (true for all call sites here).
// ---------------------------------------------------------------------------
__global__ __launch_bounds__(256)
void sgemm_xwt(const float* __restrict__ A, const float* __restrict__ Bm,
               float* __restrict__ C, int M, int N, int K) {
    __shared__ float As[16][132];
    __shared__ float Bs[16][132];
    const int tid = threadIdx.x;
    const int tx = tid & 15, ty = tid >> 4;
    const int bm = blockIdx.y * 128, bn = blockIdx.x * 128;
    const int lr = tid >> 2;          // 0..63
    const int lk = (tid & 3) << 2;    // 0,4,8,12

    const float* Aptr = A + (size_t)(bm + lr) * K + lk;
    const float* Bptr = Bm + (size_t)(bn + lr) * K + lk;

    float acc[8][8];
#pragma unroll
    for (int i = 0; i < 8; i++)
#pragma unroll
        for (int j = 0; j < 8; j++) acc[i][j] = 0.f;

    for (int k0 = 0; k0 < K; k0 += 16) {
        float4 a0 = *(const float4*)(Aptr + k0);
        float4 a1 = *(const float4*)(Aptr + (size_t)64 * K + k0);
        float4 b0 = *(const float4*)(Bptr + k0);
        float4 b1 = *(const float4*)(Bptr + (size_t)64 * K + k0);

        As[lk+0][lr]    = a0.x; As[lk+1][lr]    = a0.y; As[lk+2][lr]    = a0.z; As[lk+3][lr]    = a0.w;
        As[lk+0][lr+64] = a1.x; As[lk+1][lr+64] = a1.y; As[lk+2][lr+64] = a1.z; As[lk+3][lr+64] = a1.w;
        Bs[lk+0][lr]    = b0.x; Bs[lk+1][lr]    = b0.y; Bs[lk+2][lr]    = b0.z; Bs[lk+3][lr]    = b0.w;
        Bs[lk+0][lr+64] = b1.x; Bs[lk+1][lr+64] = b1.y; Bs[lk+2][lr+64] = b1.z; Bs[lk+3][lr+64] = b1.w;
        __syncthreads();

#pragma unroll
        for (int kk = 0; kk < 16; kk++) {
            float4 x0 = *(float4*)(&As[kk][ty*8]);
            float4 x1 = *(float4*)(&As[kk][ty*8+4]);
            float4 y0 = *(float4*)(&Bs[kk][tx*8]);
            float4 y1 = *(float4*)(&Bs[kk][tx*8+4]);
            float ar[8] = {x0.x,x0.y,x0.z,x0.w,x1.x,x1.y,x1.z,x1.w};
            float br[8] = {y0.x,y0.y,y0.z,y0.w,y1.x,y1.y,y1.z,y1.w};
#pragma unroll
            for (int i = 0; i < 8; i++)
#pragma unroll
                for (int j = 0; j < 8; j++)
                    acc[i][j] += ar[i] * br[j];
        }
        __syncthreads();
    }

#pragma unroll
    for (int i = 0; i < 8; i++) {
        float* cp = C + (size_t)(bm + ty*8 + i) * N + bn + tx*8;
        float4 c0 = make_float4(acc[i][0], acc[i][1], acc[i][2], acc[i][3]);
        float4 c1 = make_float4(acc[i][4], acc[i][5], acc[i][6], acc[i][7]);
        *(float4*)cp       = c0;
        *(float4*)(cp + 4) = c1;
    }
}

// ---------------------------------------------------------------------------
// RoPE (interleaved complex pairs: elements (2p, 2p+1) within each head)
// ---------------------------------------------------------------------------
__global__ __launch_bounds__(256)
void rope_q(float* __restrict__ q, const float* __restrict__ cs,
            const float* __restrict__ sn) {
    int idx = blockIdx.x * 256 + threadIdx.x;       // < B*S*H*64 = 2^22
    int p = idx & 63;
    int h = (idx >> 6) & (H_ - 1);
    int s = (idx >> 10) & (S_ - 1);
    int b = idx >> 21;
    float c  = cs[s*64 + p];
    float si = sn[s*64 + p];
    float2* ptr = (float2*)(q + (size_t)(b*S_ + s)*D_ + h*HD_) + p;
    float2 xv = *ptr;
    *ptr = make_float2(xv.x*c - xv.y*si, xv.x*si + xv.y*c);
}

__global__ __launch_bounds__(256)
void rope_k(float* __restrict__ k, const float* __restrict__ cs,
            const float* __restrict__ sn) {
    int idx = blockIdx.x * 256 + threadIdx.x;       // < B*S*64 = 2^17
    int p = idx & 63;
    int s = (idx >> 6) & (S_ - 1);
    int b = idx >> 17;
    float c  = cs[s*64 + p];
    float si = sn[s*64 + p];
    float2* ptr = (float2*)(k + (size_t)(b*S_ + s)*HD_) + p;
    float2 xv = *ptr;
    *ptr = make_float2(xv.x*c - xv.y*si, xv.x*si + xv.y*c);
}

// ---------------------------------------------------------------------------
// Causal flash attention, fp32, MQA (single KV head broadcast to all H).
// Per block: one (b,h) and one 64-row Q tile; stream 64-row K/V tiles.
// 256 threads: (ty 0..15, tx 0..15). Scores: thread owns 4x4 of 64x64 S-tile.
// O: thread owns rows ty*4..+3, cols tx*8..+7 of 64x128.
// ---------------------------------------------------------------------------
#define FL_SMEM ((3*64*132 + 64*68) * 4)

__global__ __launch_bounds__(256)
void flash_mqa(const float* __restrict__ q, const float* __restrict__ k,
               const float* __restrict__ v, float* __restrict__ o) {
    extern __shared__ float sm[];
    float* Qs = sm;                 // [64][132]
    float* Ks = sm + 64*132;        // [64][132]
    float* Vs = sm + 2*64*132;      // [64][132]
    float* Ps = sm + 3*64*132;      // [64][68]

    const int qtile = gridDim.x - 1 - blockIdx.x;   // heavy tiles first
    const int b = blockIdx.y >> 4, h = blockIdx.y & 15;
    const int tid = threadIdx.x;
    const int tx = tid & 15, ty = tid >> 4;
    const int qbase = qtile * 64;
    const float scale = 0.08838834764831845f;       // 1/sqrt(128)

    const float* qp = q + (size_t)(b*S_ + qbase)*D_ + h*HD_;
    for (int t = tid; t < 64*32; t += 256) {
        int r = t >> 5, c = (t & 31) << 2;
        *(float4*)(&Qs[r*132 + c]) = *(const float4*)(qp + (size_t)r*D_ + c);
    }

    float m_i[4], l_i[4], O[4][8];
#pragma unroll
    for (int i = 0; i < 4; i++) {
        m_i[i] = -INFINITY; l_i[i] = 0.f;
#pragma unroll
        for (int c = 0; c < 8; c++) O[i][c] = 0.f;
    }

    for (int kt = 0; kt <= qtile; kt++) {
        const int kbase = kt * 64;
        const float* kp = k + (size_t)(b*S_ + kbase)*HD_;
        const float* vp = v + (size_t)(b*S_ + kbase)*HD_;

        __syncthreads();   // previous tile's Ps/Vs fully consumed
        for (int t = tid; t < 64*32; t += 256) {
            int r = t >> 5, c = (t & 31) << 2;
            *(float4*)(&Ks[r*132 + c]) = *(const float4*)(kp + (size_t)r*HD_ + c);
            *(float4*)(&Vs[r*132 + c]) = *(const float4*)(vp + (size_t)r*HD_ + c);
        }
        __syncthreads();

        // ---- S = Q K^T (64x64), 4x4 per thread -------------------------------
        float acc[4][4];
#pragma unroll
        for (int i = 0; i < 4; i++)
#pragma unroll
            for (int j = 0; j < 4; j++) acc[i][j] = 0.f;

#pragma unroll 4
        for (int d = 0; d < 128; d += 4) {
            float4 av[4], bv[4];
#pragma unroll
            for (int ii = 0; ii < 4; ii++) av[ii] = *(float4*)(&Qs[(ty*4+ii)*132 + d]);
#pragma unroll
            for (int jj = 0; jj < 4; jj++) bv[jj] = *(float4*)(&Ks[(tx*4+jj)*132 + d]);
#pragma unroll
            for (int ii = 0; ii < 4; ii++)
#pragma unroll
                for (int jj = 0; jj < 4; jj++)
                    acc[ii][jj] += av[ii].x*bv[jj].x + av[ii].y*bv[jj].y
                                 + av[ii].z*bv[jj].z + av[ii].w*bv[jj].w;
        }

        // ---- online softmax (row state replicated across the 16 tx lanes) ----
        const bool diag = (kt == qtile);
#pragma unroll
        for (int ii = 0; ii < 4; ii++) {
            int r = ty*4 + ii;
            float rowmax = -INFINITY;
#pragma unroll
            for (int jj = 0; jj < 4; jj++) {
                int c = tx*4 + jj;
                float sv = acc[ii][jj] * scale;
                if (diag && c > r) sv = -INFINITY;
                acc[ii][jj] = sv;
                rowmax = fmaxf(rowmax, sv);
            }
#pragma unroll
            for (int off = 8; off > 0; off >>= 1)
                rowmax = fmaxf(rowmax, __shfl_xor_sync(0xffffffffu, rowmax, off));
            float mnew  = fmaxf(m_i[ii], rowmax);
            float alpha = __expf(m_i[ii] - mnew);
            float rsum = 0.f;
#pragma unroll
            for (int jj = 0; jj < 4; jj++) {
                float p = __expf(acc[ii][jj] - mnew);
                Ps[r*68 + tx*4 + jj] = p;
                rsum += p;
            }
#pragma unroll
            for (int off = 8; off > 0; off >>= 1)
                rsum += __shfl_xor_sync(0xffffffffu, rsum, off);
            l_i[ii] = l_i[ii]*alpha + rsum;
            m_i[ii] = mnew;
#pragma unroll
            for (int c = 0; c < 8; c++) O[ii][c] *= alpha;
        }
        __syncthreads();   // Ps complete

        // ---- O += P @ V ------------------------------------------------------
#pragma unroll 2
        for (int j = 0; j < 64; j++) {
            float4 v0 = *(float4*)(&Vs[j*132 + tx*8]);
            float4 v1 = *(float4*)(&Vs[j*132 + tx*8 + 4]);
#pragma unroll
            for (int ii = 0; ii < 4; ii++) {
                float p = Ps[(ty*4+ii)*68 + j];
                O[ii][0] += p*v0.x; O[ii][1] += p*v0.y; O[ii][2] += p*v0.z; O[ii][3] += p*v0.w;
                O[ii][4] += p*v1.x; O[ii][5] += p*v1.y; O[ii][6] += p*v1.z; O[ii][7] += p*v1.w;
            }
        }
    }

    // ---- epilogue: normalize and store in [B,S,H*HD] layout -----------------
    float* op = o + (size_t)(b*S_ + qbase)*D_ + h*HD_;
#pragma unroll
    for (int ii = 0; ii < 4; ii++) {
        int r = ty*4 + ii;
        float inv = 1.f / l_i[ii];
        float4 c0 = make_float4(O[ii][0]*inv, O[ii][1]*inv, O[ii][2]*inv, O[ii][3]*inv);
        float4 c1 = make_float4(O[ii][4]*inv, O[ii][5]*inv, O[ii][6]*inv, O[ii][7]*inv);
        *(float4*)(op + (size_t)r*D_ + tx*8)     = c0;
        *(float4*)(op + (size_t)r*D_ + tx*8 + 4) = c1;
    }
}

// ---------------------------------------------------------------------------
extern "C" void kernel_launch(void* const* d_in, const int* in_sizes, int n_in,
                              void* d_out, int out_size) {
    const float* x  = (const float*)d_in[0];
    const float* Wq = (const float*)d_in[1];
    const float* Wk = (const float*)d_in[2];
    const float* Wv = (const float*)d_in[3];
    const float* Wo = (const float*)d_in[4];
    const float* rc = (const float*)d_in[5];
    const float* rs = (const float*)d_in[6];
    float* out = (float*)d_out;

    float *qb, *kb, *vb, *ab;
    cudaGetSymbolAddress((void**)&qb, g_q);
    cudaGetSymbolAddress((void**)&kb, g_k);
    cudaGetSymbolAddress((void**)&vb, g_v);
    cudaGetSymbolAddress((void**)&ab, g_attn);

    cudaFuncSetAttribute(flash_mqa, cudaFuncAttributeMaxDynamicSharedMemorySize, FL_SMEM);

    const int M = B_ * S_;   // 4096 tokens
    sgemm_xwt<<<dim3(D_/128, M/128), 256>>>(x, Wq, qb, M, D_, D_);
    sgemm_xwt<<<dim3(1,      M/128), 256>>>(x, Wk, kb, M, HD_, D_);
    sgemm_xwt<<<dim3(1,      M/128), 256>>>(x, Wv, vb, M, HD_, D_);

    rope_q<<<(B_*S_*H_*64)/256, 256>>>(qb, rc, rs);
    rope_k<<<(B_*S_*64)/256,    256>>>(kb, rc, rs);

    flash_mqa<<<dim3(S_/64, B_*H_), 256, FL_SMEM>>>(qb, kb, vb, ab);

    sgemm_xwt<<<dim3(D_/128, M/128), 256>>>(ab, Wo, out, M, D_, D_);
}

// round 5
// speedup vs baseline: 1.4099x; 1.4099x over previous
#include <cuda_runtime.h>
#include <cuda_bf16.h>
#include <math.h>
#include <stdint.h>

#define B_  2
#define S_  2048
#define D_  2048
#define H_  16
#define HD_ 128
#define MTOK (B_*S_)          // 4096 tokens

// ---------------- scratch (static device globals; no runtime allocation) ----
__device__ float g_q[MTOK*D_];            // [B,S,H,HD] post-proj / post-RoPE
__device__ float g_kv[MTOK*256];          // k cols 0..127, v cols 128..255
__device__ float g_attn[MTOK*D_];         // attention output [B,S,H*HD]

__device__ __nv_bfloat16 g_xhi[MTOK*D_],  g_xlo[MTOK*D_];
__device__ __nv_bfloat16 g_wqhi[D_*D_],   g_wqlo[D_*D_];
__device__ __nv_bfloat16 g_wkvhi[256*D_], g_wkvlo[256*D_];
__device__ __nv_bfloat16 g_wohi[D_*D_],   g_wolo[D_*D_];
__device__ __nv_bfloat16 g_ahi[MTOK*D_],  g_alo[MTOK*D_];

// =========================== helpers =======================================
__device__ __forceinline__ uint32_t smem_u32(const void* p) {
    uint32_t a;
    asm("{ .reg .u64 t; cvta.to.shared.u64 t, %1; cvt.u32.u64 %0, t; }"
        : "=r"(a) : "l"(p));
    return a;
}

__device__ __forceinline__ void ldsm4(uint32_t* r, uint32_t addr) {
    asm volatile("ldmatrix.sync.aligned.m8n8.x4.shared.b16 {%0,%1,%2,%3}, [%4];"
        : "=r"(r[0]), "=r"(r[1]), "=r"(r[2]), "=r"(r[3]) : "r"(addr));
}

__device__ __forceinline__ void mma16816(float* c, const uint32_t* a,
                                         uint32_t b0, uint32_t b1) {
    asm volatile(
        "mma.sync.aligned.m16n8k16.row.col.f32.bf16.bf16.f32 "
        "{%0,%1,%2,%3}, {%4,%5,%6,%7}, {%8,%9}, {%0,%1,%2,%3};"
        : "+f"(c[0]), "+f"(c[1]), "+f"(c[2]), "+f"(c[3])
        : "r"(a[0]), "r"(a[1]), "r"(a[2]), "r"(a[3]), "r"(b0), "r"(b1));
}

// =========================== bf16 split conversion =========================
__global__ __launch_bounds__(256)
void split_bf16(const float* __restrict__ src, __nv_bfloat16* __restrict__ hi,
                __nv_bfloat16* __restrict__ lo, int n4) {
    int i = blockIdx.x * 256 + threadIdx.x;
    if (i >= n4) return;
    float4 v = ((const float4*)src)[i];
    __nv_bfloat16 h0 = __float2bfloat16(v.x), h1 = __float2bfloat16(v.y);
    __nv_bfloat16 h2 = __float2bfloat16(v.z), h3 = __float2bfloat16(v.w);
    __nv_bfloat16 l0 = __float2bfloat16(v.x - __bfloat162float(h0));
    __nv_bfloat16 l1 = __float2bfloat16(v.y - __bfloat162float(h1));
    __nv_bfloat16 l2 = __float2bfloat16(v.z - __bfloat162float(h2));
    __nv_bfloat16 l3 = __float2bfloat16(v.w - __bfloat162float(h3));
    __nv_bfloat162 hp0; hp0.x = h0; hp0.y = h1;
    __nv_bfloat162 hp1; hp1.x = h2; hp1.y = h3;
    __nv_bfloat162 lp0; lp0.x = l0; lp0.y = l1;
    __nv_bfloat162 lp1; lp1.x = l2; lp1.y = l3;
    ((__nv_bfloat162*)hi)[2*i]   = hp0;
    ((__nv_bfloat162*)hi)[2*i+1] = hp1;
    ((__nv_bfloat162*)lo)[2*i]   = lp0;
    ((__nv_bfloat162*)lo)[2*i+1] = lp1;
}

// =========================== mma.sync split GEMM ===========================
// C[M x N] = (Ahi+Alo)(Bhi+Blo)^T dropping lo*lo. Both operands K-major.
// CTA tile 128x128, BK=32. 256 threads = 8 warps (4 over M x 2 over N),
// warp tile 32x64 via m16n8k16. Smem rows padded to 40 bf16 (conflict-free).
#define LDSW 40

__global__ __launch_bounds__(256)
void gemm_mma(const __nv_bfloat16* __restrict__ Ahi, const __nv_bfloat16* __restrict__ Alo,
              const __nv_bfloat16* __restrict__ Bhi, const __nv_bfloat16* __restrict__ Blo,
              float* __restrict__ C, int K, int ldc) {
    __shared__ __align__(16) __nv_bfloat16 sm[4][128 * LDSW];
    const int tid = threadIdx.x, wid = tid >> 5, lane = tid & 31;
    const int bm = blockIdx.y * 128, bn = blockIdx.x * 128;
    const int wm = (wid & 3) * 32;       // warp M offset
    const int wn = (wid >> 2) * 64;      // warp N offset

    // gmem->reg prefetch mapping: per matrix 2 float4/thread
    const int lr = tid >> 2;             // 0..63
    const int lc = (tid & 3) * 8;        // 0,8,16,24
    const __nv_bfloat16* gp[4];
    gp[0] = Ahi + (size_t)(bm + lr) * K + lc;
    gp[1] = Alo + (size_t)(bm + lr) * K + lc;
    gp[2] = Bhi + (size_t)(bn + lr) * K + lc;
    gp[3] = Blo + (size_t)(bn + lr) * K + lc;

    uint32_t sb[4];
#pragma unroll
    for (int m = 0; m < 4; m++) sb[m] = smem_u32(&sm[m][0]);

    float acc[2][8][4];
#pragma unroll
    for (int mf = 0; mf < 2; mf++)
#pragma unroll
        for (int nf = 0; nf < 8; nf++)
#pragma unroll
            for (int i = 0; i < 4; i++) acc[mf][nf][i] = 0.f;

    float4 pref[4][2];
#pragma unroll
    for (int m = 0; m < 4; m++) {
        pref[m][0] = *(const float4*)(gp[m]);
        pref[m][1] = *(const float4*)(gp[m] + (size_t)64 * K);
    }

    const int g = lane >> 3;             // ldmatrix address group 0..3
    const int l7 = lane & 7;
    const int niter = K / 32;
    for (int it = 0; it < niter; it++) {
        __syncthreads();
#pragma unroll
        for (int m = 0; m < 4; m++) {
            *(float4*)(&sm[m][lr * LDSW + lc])        = pref[m][0];
            *(float4*)(&sm[m][(lr + 64) * LDSW + lc]) = pref[m][1];
        }
        __syncthreads();

        {   // prefetch next chunk; clamp offset so no OOB address ever forms
            const int knext = (it + 1 < niter) ? (it + 1) * 32 : 0;
#pragma unroll
            for (int m = 0; m < 4; m++) {
                pref[m][0] = *(const float4*)(gp[m] + knext);
                pref[m][1] = *(const float4*)(gp[m] + (size_t)64 * K + knext);
            }
        }

#pragma unroll
        for (int kk = 0; kk < 2; kk++) {
            // A fragments (hi, lo) for both 16-row m-frags
            uint32_t ah[2][4], al[2][4];
#pragma unroll
            for (int mf = 0; mf < 2; mf++) {
                int row = wm + mf * 16 + (g & 1) * 8 + l7;
                int col = kk * 16 + (g >> 1) * 8;
                uint32_t off = (uint32_t)(row * LDSW + col) * 2;
                ldsm4(ah[mf], sb[0] + off);
                ldsm4(al[mf], sb[1] + off);
            }
            // B fragments: each x4 covers two n8 frags (both k-halves)
#pragma unroll
            for (int nf = 0; nf < 8; nf += 2) {
                int row = wn + nf * 8 + (g & 2) * 4 + l7;
                int col = kk * 16 + (g & 1) * 8;
                uint32_t off = (uint32_t)(row * LDSW + col) * 2;
                uint32_t bh[4], bl[4];
                ldsm4(bh, sb[2] + off);
                ldsm4(bl, sb[3] + off);
#pragma unroll
                for (int mf = 0; mf < 2; mf++) {
                    mma16816(acc[mf][nf],     ah[mf], bh[0], bh[1]);
                    mma16816(acc[mf][nf],     al[mf], bh[0], bh[1]);
                    mma16816(acc[mf][nf],     ah[mf], bl[0], bl[1]);
                    mma16816(acc[mf][nf + 1], ah[mf], bh[2], bh[3]);
                    mma16816(acc[mf][nf + 1], al[mf], bh[2], bh[3]);
                    mma16816(acc[mf][nf + 1], ah[mf], bl[2], bl[3]);
                }
            }
        }
    }

    // epilogue: thread holds c[m = lane/4 (+8), n = (lane%4)*2 (+1)]
    const int mrow = lane >> 2, ncol = (lane & 3) * 2;
#pragma unroll
    for (int mf = 0; mf < 2; mf++)
#pragma unroll
        for (int nf = 0; nf < 8; nf++) {
            int mg = bm + wm + mf * 16 + mrow;
            int ng = bn + wn + nf * 8 + ncol;
            *(float2*)(C + (size_t)mg * ldc + ng) =
                make_float2(acc[mf][nf][0], acc[mf][nf][1]);
            *(float2*)(C + (size_t)(mg + 8) * ldc + ng) =
                make_float2(acc[mf][nf][2], acc[mf][nf][3]);
        }
}

// =========================== RoPE ==========================================
__global__ __launch_bounds__(256)
void rope_q(float* __restrict__ q, const float* __restrict__ cs,
            const float* __restrict__ sn) {
    int idx = blockIdx.x * 256 + threadIdx.x;       // < B*S*H*64 = 2^22
    int p = idx & 63;
    int h = (idx >> 6) & (H_ - 1);
    int s = (idx >> 10) & (S_ - 1);
    int b = idx >> 21;
    float c  = cs[s*64 + p];
    float si = sn[s*64 + p];
    float2* ptr = (float2*)(q + (size_t)(b*S_ + s)*D_ + h*HD_) + p;
    float2 xv = *ptr;
    *ptr = make_float2(xv.x*c - xv.y*si, xv.x*si + xv.y*c);
}

__global__ __launch_bounds__(256)
void rope_k(float* __restrict__ kv, const float* __restrict__ cs,
            const float* __restrict__ sn) {
    int idx = blockIdx.x * 256 + threadIdx.x;       // < B*S*64 = 2^18
    int p = idx & 63;
    int s = (idx >> 6) & (S_ - 1);
    int b = idx >> 17;
    float c  = cs[s*64 + p];
    float si = sn[s*64 + p];
    float2* ptr = (float2*)(kv + (size_t)(b*S_ + s)*256) + p;   // k = cols 0..127
    float2 xv = *ptr;
    *ptr = make_float2(xv.x*c - xv.y*si, xv.x*si + xv.y*c);
}

// =========================== flash attention (SIMT fp32) ===================
#define FL_SMEM ((3*64*132 + 64*68) * 4)

__global__ __launch_bounds__(256)
void flash_mqa(const float* __restrict__ q, const float* __restrict__ kv,
               float* __restrict__ o) {
    extern __shared__ float sm[];
    float* Qs = sm;                 // [64][132]
    float* Ks = sm + 64*132;
    float* Vs = sm + 2*64*132;
    float* Ps = sm + 3*64*132;      // [64][68]

    const int qtile = gridDim.x - 1 - blockIdx.x;   // heavy tiles first
    const int b = blockIdx.y >> 4, h = blockIdx.y & 15;
    const int tid = threadIdx.x;
    const int tx = tid & 15, ty = tid >> 4;
    const int qbase = qtile * 64;
    const float scale = 0.08838834764831845f;       // 1/sqrt(128)

    const float* qp = q + (size_t)(b*S_ + qbase)*D_ + h*HD_;
    for (int t = tid; t < 64*32; t += 256) {
        int r = t >> 5, c = (t & 31) << 2;
        *(float4*)(&Qs[r*132 + c]) = *(const float4*)(qp + (size_t)r*D_ + c);
    }

    float m_i[4], l_i[4], O[4][8];
#pragma unroll
    for (int i = 0; i < 4; i++) {
        m_i[i] = -INFINITY; l_i[i] = 0.f;
#pragma unroll
        for (int c = 0; c < 8; c++) O[i][c] = 0.f;
    }

    for (int kt = 0; kt <= qtile; kt++) {
        const int kbase = kt * 64;
        const float* kp = kv + (size_t)(b*S_ + kbase)*256;   // k cols 0..127, v 128..255

        __syncthreads();
        for (int t = tid; t < 64*32; t += 256) {
            int r = t >> 5, c = (t & 31) << 2;
            *(float4*)(&Ks[r*132 + c]) = *(const float4*)(kp + (size_t)r*256 + c);
            *(float4*)(&Vs[r*132 + c]) = *(const float4*)(kp + (size_t)r*256 + 128 + c);
        }
        __syncthreads();

        float acc[4][4];
#pragma unroll
        for (int i = 0; i < 4; i++)
#pragma unroll
            for (int j = 0; j < 4; j++) acc[i][j] = 0.f;

#pragma unroll 4
        for (int d = 0; d < 128; d += 4) {
            float4 av[4], bv[4];
#pragma unroll
            for (int ii = 0; ii < 4; ii++) av[ii] = *(float4*)(&Qs[(ty*4+ii)*132 + d]);
#pragma unroll
            for (int jj = 0; jj < 4; jj++) bv[jj] = *(float4*)(&Ks[(tx*4+jj)*132 + d]);
#pragma unroll
            for (int ii = 0; ii < 4; ii++)
#pragma unroll
                for (int jj = 0; jj < 4; jj++)
                    acc[ii][jj] += av[ii].x*bv[jj].x + av[ii].y*bv[jj].y
                                 + av[ii].z*bv[jj].z + av[ii].w*bv[jj].w;
        }

        const bool diag = (kt == qtile);
#pragma unroll
        for (int ii = 0; ii < 4; ii++) {
            int r = ty*4 + ii;
            float rowmax = -INFINITY;
#pragma unroll
            for (int jj = 0; jj < 4; jj++) {
                int c = tx*4 + jj;
                float sv = acc[ii][jj] * scale;
                if (diag && c > r) sv = -INFINITY;
                acc[ii][jj] = sv;
                rowmax = fmaxf(rowmax, sv);
            }
#pragma unroll
            for (int off = 8; off > 0; off >>= 1)
                rowmax = fmaxf(rowmax, __shfl_xor_sync(0xffffffffu, rowmax, off));
            float mnew  = fmaxf(m_i[ii], rowmax);
            float alpha = __expf(m_i[ii] - mnew);
            float rsum = 0.f;
#pragma unroll
            for (int jj = 0; jj < 4; jj++) {
                float p = __expf(acc[ii][jj] - mnew);
                Ps[r*68 + tx*4 + jj] = p;
                rsum += p;
            }
#pragma unroll
            for (int off = 8; off > 0; off >>= 1)
                rsum += __shfl_xor_sync(0xffffffffu, rsum, off);
            l_i[ii] = l_i[ii]*alpha + rsum;
            m_i[ii] = mnew;
#pragma unroll
            for (int c = 0; c < 8; c++) O[ii][c] *= alpha;
        }
        __syncthreads();

#pragma unroll 2
        for (int j = 0; j < 64; j++) {
            float4 v0 = *(float4*)(&Vs[j*132 + tx*8]);
            float4 v1 = *(float4*)(&Vs[j*132 + tx*8 + 4]);
#pragma unroll
            for (int ii = 0; ii < 4; ii++) {
                float p = Ps[(ty*4+ii)*68 + j];
                O[ii][0] += p*v0.x; O[ii][1] += p*v0.y; O[ii][2] += p*v0.z; O[ii][3] += p*v0.w;
                O[ii][4] += p*v1.x; O[ii][5] += p*v1.y; O[ii][6] += p*v1.z; O[ii][7] += p*v1.w;
            }
        }
    }

    float* op = o + (size_t)(b*S_ + qbase)*D_ + h*HD_;
#pragma unroll
    for (int ii = 0; ii < 4; ii++) {
        int r = ty*4 + ii;
        float inv = 1.f / l_i[ii];
        float4 c0 = make_float4(O[ii][0]*inv, O[ii][1]*inv, O[ii][2]*inv, O[ii][3]*inv);
        float4 c1 = make_float4(O[ii][4]*inv, O[ii][5]*inv, O[ii][6]*inv, O[ii][7]*inv);
        *(float4*)(op + (size_t)r*D_ + tx*8)     = c0;
        *(float4*)(op + (size_t)r*D_ + tx*8 + 4) = c1;
    }
}

// ===========================================================================
extern "C" void kernel_launch(void* const* d_in, const int* in_sizes, int n_in,
                              void* d_out, int out_size) {
    const float* x  = (const float*)d_in[0];
    const float* Wq = (const float*)d_in[1];
    const float* Wk = (const float*)d_in[2];
    const float* Wv = (const float*)d_in[3];
    const float* Wo = (const float*)d_in[4];
    const float* rc = (const float*)d_in[5];
    const float* rs = (const float*)d_in[6];
    float* out = (float*)d_out;

    float *qb, *kvb, *ab;
    __nv_bfloat16 *xhi, *xlo, *wqhi, *wqlo, *wkvhi, *wkvlo, *wohi, *wolo, *ahi, *alo;
    cudaGetSymbolAddress((void**)&qb,  g_q);
    cudaGetSymbolAddress((void**)&kvb, g_kv);
    cudaGetSymbolAddress((void**)&ab,  g_attn);
    cudaGetSymbolAddress((void**)&xhi, g_xhi);   cudaGetSymbolAddress((void**)&xlo, g_xlo);
    cudaGetSymbolAddress((void**)&wqhi,g_wqhi);  cudaGetSymbolAddress((void**)&wqlo,g_wqlo);
    cudaGetSymbolAddress((void**)&wkvhi,g_wkvhi);cudaGetSymbolAddress((void**)&wkvlo,g_wkvlo);
    cudaGetSymbolAddress((void**)&wohi,g_wohi);  cudaGetSymbolAddress((void**)&wolo,g_wolo);
    cudaGetSymbolAddress((void**)&ahi, g_ahi);   cudaGetSymbolAddress((void**)&alo, g_alo);

    cudaFuncSetAttribute(flash_mqa, cudaFuncAttributeMaxDynamicSharedMemorySize, FL_SMEM);

    // ---- bf16 hi/lo conversions -------------------------------------------
    split_bf16<<<(MTOK*D_/4 + 255)/256, 256>>>(x,  xhi,  xlo,  MTOK*D_/4);
    split_bf16<<<(D_*D_/4   + 255)/256, 256>>>(Wq, wqhi, wqlo, D_*D_/4);
    split_bf16<<<(HD_*D_/4  + 255)/256, 256>>>(Wk, wkvhi,          wkvlo,          HD_*D_/4);
    split_bf16<<<(HD_*D_/4  + 255)/256, 256>>>(Wv, wkvhi + 128*D_, wkvlo + 128*D_, HD_*D_/4);
    split_bf16<<<(D_*D_/4   + 255)/256, 256>>>(Wo, wohi, wolo, D_*D_/4);

    // ---- projections on tensor cores (mma.sync) ---------------------------
    gemm_mma<<<dim3(D_/128, MTOK/128), 256>>>(xhi, xlo, wqhi, wqlo, qb, D_, D_);
    gemm_mma<<<dim3(2,      MTOK/128), 256>>>(xhi, xlo, wkvhi, wkvlo, kvb, D_, 256);

    // ---- RoPE -------------------------------------------------------------
    rope_q<<<(B_*S_*H_*64)/256, 256>>>(qb,  rc, rs);
    rope_k<<<(B_*S_*64)/256,    256>>>(kvb, rc, rs);

    // ---- attention --------------------------------------------------------
    flash_mqa<<<dim3(S_/64, B_*H_), 256, FL_SMEM>>>(qb, kvb, ab);

    // ---- output projection ------------------------------------------------
    split_bf16<<<(MTOK*D_/4 + 255)/256, 256>>>(ab, ahi, alo, MTOK*D_/4);
    gemm_mma<<<dim3(D_/128, MTOK/128), 256>>>(ahi, alo, wohi, wolo, out, D_, D_);
}